// round 16
// baseline (speedup 1.0000x reference)
#include <cuda_runtime.h>
#include <cstdint>

#define NU    100000
#define NI    50000
#define NN    150000            // NU + NI
#define D     64
#define NNZ_  8000000
#define HOPS  3
#define CAP   160               // padded row capacity; P(Poisson(53)>160) ~ 0

// Static device scratch (per harness rules: no allocations).
__device__ int  g_cnt[NN];                      // per-row edge count
__device__ int2 g_edges[(size_t)NN * CAP];      // padded rows: {col|mask<<18, val*2}

// ---------------------------------------------------------------------------
// Dummy: shifts launch indices so ncu (-s 5 -c 1) profiles hop 2.
// ---------------------------------------------------------------------------
__global__ void dummy_kernel() {
    if (threadIdx.x == 0 && blockIdx.x == 0) g_cnt[0] = 0;   // overwritten by init
}

// ---------------------------------------------------------------------------
// Init: out[:, 0, :] = concat(user, item); zero row counters.
// ---------------------------------------------------------------------------
__global__ void init_kernel(const float* __restrict__ user,
                            const float* __restrict__ item,
                            float* __restrict__ out) {
    int t = blockIdx.x * blockDim.x + threadIdx.x;
    if (t < NN) g_cnt[t] = 0;
    const int total = NN * D / 16;          // 600,000 threads
    if (t >= total) return;
    const int base   = t * 4;
    const int userF4 = NU * D / 4;
    float4 v[4];
    #pragma unroll
    for (int i = 0; i < 4; ++i) {
        int idx = base + i;
        v[i] = (idx < userF4) ? ((const float4*)user)[idx]
                              : ((const float4*)item)[idx - userF4];
    }
    const int node = base >> 4;
    const int f4   = base & 15;
    #pragma unroll
    for (int i = 0; i < 4; ++i)
        ((float4*)out)[(size_t)node * 64 + f4 + i] = v[i];
}

// ---------------------------------------------------------------------------
// ONE-PASS build (no hist, no scan): pos = row*CAP + atomicAdd(cnt[row]).
// 4 independent chains per thread to hide atomic+scattered-store latency.
// Record packs {col | keepmask<<18, val*2} (col < 2^18).
// ---------------------------------------------------------------------------
__global__ void build_kernel(const int*   __restrict__ rows,
                             const int*   __restrict__ cols,
                             const float* __restrict__ vals,
                             const float* __restrict__ erand) {
    int t  = blockIdx.x * blockDim.x + threadIdx.x;
    int nt = gridDim.x * blockDim.x;
    for (int base = t; base < NNZ_; base += 4 * nt) {
        int  e[4]; bool g[4]; int r[4]; int2 rec[4];
        #pragma unroll
        for (int k = 0; k < 4; ++k) { e[k] = base + k * nt; g[k] = e[k] < NNZ_; }
        #pragma unroll
        for (int k = 0; k < 4; ++k) {
            if (g[k]) {
                int   ee = e[k];
                r[k]     = __ldcs(rows + ee);
                int   c  = __ldcs(cols + ee);
                float v  = __ldcs(vals + ee) * 2.0f;    // 1/(1-0.5)
                int m = (__ldcs(erand + ee)            >= 0.5f ? 1 : 0)
                      | (__ldcs(erand + NNZ_ + ee)     >= 0.5f ? 2 : 0)
                      | (__ldcs(erand + 2 * NNZ_ + ee) >= 0.5f ? 4 : 0);
                rec[k] = make_int2(c | (m << 18), __float_as_int(v));
            }
        }
        int p[4];
        #pragma unroll
        for (int k = 0; k < 4; ++k)
            if (g[k]) p[k] = atomicAdd(&g_cnt[r[k]], 1);
        #pragma unroll
        for (int k = 0; k < 4; ++k)
            if (g[k]) __stcs(&g_edges[(size_t)r[k] * CAP + p[k]],
                             *(const int2*)&rec[k]);
    }
}

// ---------------------------------------------------------------------------
// Padded-ELL SpMM + fused message dropout. FULL WARP PER ROW, float2/lane.
// NO ballot / ffs / shfl: every lane does a UNIFORM __ldg of the edge record
// (broadcast, L1-hot — a row's ~53 records span 2-3 cache lines). The keep
// test is warp-uniform, so dropped edges skip the gather with a divergence-
// free branch. Unroll x4: 4 uniform loads + 4 predicated gathers batched.
// Row owned by one warp -> register accumulator, no atomics, fused dropout.
// ---------------------------------------------------------------------------
__global__ void spmm_ell_kernel(const float* __restrict__ src,   // = out + hop*64
                                const float* __restrict__ mrand, // hop slice
                                float* __restrict__ out,
                                int hop) {
    const int lane = threadIdx.x & 31;
    const int gw   = (blockIdx.x * blockDim.x + threadIdx.x) >> 5;
    const int nw   = (gridDim.x * blockDim.x) >> 5;
    const int hopbit = 1 << (18 + hop);
    const float sc = 1.0f / 0.9f;

    for (int r = gw; r < NN; r += nw) {
        const int n = __ldg(&g_cnt[r]);
        const int2* __restrict__ ebase = g_edges + (size_t)r * CAP;
        float accx = 0.f, accy = 0.f;
        int j = 0;
        for (; j + 4 <= n; j += 4) {
            int2 e0 = __ldg(ebase + j);
            int2 e1 = __ldg(ebase + j + 1);
            int2 e2 = __ldg(ebase + j + 2);
            int2 e3 = __ldg(ebase + j + 3);
            bool k0 = (e0.x & hopbit) != 0;
            bool k1 = (e1.x & hopbit) != 0;
            bool k2 = (e2.x & hopbit) != 0;
            bool k3 = (e3.x & hopbit) != 0;
            float2 x0, x1, x2, x3;
            if (k0) x0 = __ldg((const float2*)(src + (size_t)(e0.x & 0x3FFFF) * 256) + lane);
            if (k1) x1 = __ldg((const float2*)(src + (size_t)(e1.x & 0x3FFFF) * 256) + lane);
            if (k2) x2 = __ldg((const float2*)(src + (size_t)(e2.x & 0x3FFFF) * 256) + lane);
            if (k3) x3 = __ldg((const float2*)(src + (size_t)(e3.x & 0x3FFFF) * 256) + lane);
            if (k0) { float v = __int_as_float(e0.y); accx += v * x0.x; accy += v * x0.y; }
            if (k1) { float v = __int_as_float(e1.y); accx += v * x1.x; accy += v * x1.y; }
            if (k2) { float v = __int_as_float(e2.y); accx += v * x2.x; accy += v * x2.y; }
            if (k3) { float v = __int_as_float(e3.y); accx += v * x3.x; accy += v * x3.y; }
        }
        for (; j < n; ++j) {
            int2 e = __ldg(ebase + j);
            if (e.x & hopbit) {
                float v = __int_as_float(e.y);
                float2 x = __ldg((const float2*)(src + (size_t)(e.x & 0x3FFFF) * 256) + lane);
                accx += v * x.x;
                accy += v * x.y;
            }
        }
        // fused message dropout + write next hop slice (sole owner of row r)
        float2 m = __ldcs((const float2*)(mrand + (size_t)r * 64) + lane);
        float2 o;
        o.x = (m.x >= 0.1f) ? accx * sc : 0.f;
        o.y = (m.y >= 0.1f) ? accy * sc : 0.f;
        ((float2*)(out + (size_t)r * 256 + (size_t)(hop + 1) * 64))[lane] = o;
    }
}

// ---------------------------------------------------------------------------
extern "C" void kernel_launch(void* const* d_in, const int* in_sizes, int n_in,
                              void* d_out, int out_size) {
    const float* user  = (const float*)d_in[0];
    const float* item  = (const float*)d_in[1];
    const int*   rows  = (const int*)  d_in[2];
    const int*   cols  = (const int*)  d_in[3];
    const float* vals  = (const float*)d_in[4];
    const float* erand = (const float*)d_in[5];
    const float* mrand = (const float*)d_in[6];
    float*       out   = (float*)d_out;

    const int totalT    = NN * D / 16;      // 600,000
    const int ewThreads = 256;
    const int ewBlocks  = (totalT + ewThreads - 1) / ewThreads;

    const int gsBlocks  = 148 * 32;
    const int gsThreads = 256;

    // Launches: 0 dummy, 1 init, 2 build, 3 hop0, 4 hop1, 5 hop2
    // (ncu -s 5 -c 1 -> profiles spmm_ell hop 2)
    dummy_kernel<<<1, 32>>>();
    init_kernel<<<ewBlocks, ewThreads>>>(user, item, out);
    build_kernel<<<gsBlocks, gsThreads>>>(rows, cols, vals, erand);
    for (int hop = 0; hop < HOPS; ++hop) {
        spmm_ell_kernel<<<gsBlocks, gsThreads>>>(out + (size_t)hop * 64,
                                                 mrand + (size_t)hop * NN * D,
                                                 out, hop);
    }
}

// round 17
// speedup vs baseline: 1.6382x; 1.6382x over previous
#include <cuda_runtime.h>
#include <cstdint>

#define NU    100000
#define NI    50000
#define NN    150000            // NU + NI
#define D     64
#define NNZ_  8000000
#define HOPS  3
#define CAP2  80                // per-hop kept edges per row: mean 26.7, max ~53

// Static device scratch (per harness rules: no allocations).
__device__ int  g_cnt3[HOPS * NN];                       // per-(hop,row) counts
__device__ int2 g_edges3[(size_t)HOPS * NN * CAP2];      // compacted {col, val*2}

// ---------------------------------------------------------------------------
// Dummy: shifts launch indices so ncu (-s 5 -c 1) profiles hop 2.
// ---------------------------------------------------------------------------
__global__ void dummy_kernel() {
    if (threadIdx.x == 0 && blockIdx.x == 0) g_cnt3[0] = 0;  // re-zeroed by init
}

// ---------------------------------------------------------------------------
// Init: out[:, 0, :] = concat(user, item); zero all per-hop row counters.
// ---------------------------------------------------------------------------
__global__ void init_kernel(const float* __restrict__ user,
                            const float* __restrict__ item,
                            float* __restrict__ out) {
    int t = blockIdx.x * blockDim.x + threadIdx.x;
    if (t < HOPS * NN) g_cnt3[t] = 0;       // 450,000 < 600,000 threads
    const int total = NN * D / 16;          // 600,000 threads
    if (t >= total) return;
    const int base   = t * 4;
    const int userF4 = NU * D / 4;
    float4 v[4];
    #pragma unroll
    for (int i = 0; i < 4; ++i) {
        int idx = base + i;
        v[i] = (idx < userF4) ? ((const float4*)user)[idx]
                              : ((const float4*)item)[idx - userF4];
    }
    const int node = base >> 4;
    const int f4   = base & 15;
    #pragma unroll
    for (int i = 0; i < 4; ++i)
        ((float4*)out)[(size_t)node * 64 + f4 + i] = v[i];
}

// ---------------------------------------------------------------------------
// ONE-PASS build of THREE per-hop compacted ELL lists:
//   for each hop where edge is kept: pos = atomicAdd(cnt3[hop][row]);
//   edges3[hop][row*CAP2 + pos] = {col, val*2}.
// 4 independent edge chains per thread to hide atomic+store latency.
// ---------------------------------------------------------------------------
__global__ void build_kernel(const int*   __restrict__ rows,
                             const int*   __restrict__ cols,
                             const float* __restrict__ vals,
                             const float* __restrict__ erand) {
    int t  = blockIdx.x * blockDim.x + threadIdx.x;
    int nt = gridDim.x * blockDim.x;
    for (int base = t; base < NNZ_; base += 4 * nt) {
        int  e[4]; bool g[4]; int r[4]; int2 rec[4]; int m[4];
        #pragma unroll
        for (int k = 0; k < 4; ++k) { e[k] = base + k * nt; g[k] = e[k] < NNZ_; }
        #pragma unroll
        for (int k = 0; k < 4; ++k) {
            if (g[k]) {
                int   ee = e[k];
                r[k]     = __ldcs(rows + ee);
                int   c  = __ldcs(cols + ee);
                float v  = __ldcs(vals + ee) * 2.0f;    // 1/(1-0.5)
                m[k] = (__ldcs(erand + ee)            >= 0.5f ? 1 : 0)
                     | (__ldcs(erand + NNZ_ + ee)     >= 0.5f ? 2 : 0)
                     | (__ldcs(erand + 2 * NNZ_ + ee) >= 0.5f ? 4 : 0);
                rec[k] = make_int2(c, __float_as_int(v));
            }
        }
        #pragma unroll
        for (int h = 0; h < HOPS; ++h) {
            int p[4];
            #pragma unroll
            for (int k = 0; k < 4; ++k)
                if (g[k] && (m[k] >> h & 1))
                    p[k] = atomicAdd(&g_cnt3[h * NN + r[k]], 1);
            #pragma unroll
            for (int k = 0; k < 4; ++k)
                if (g[k] && (m[k] >> h & 1))
                    __stcs(&g_edges3[((size_t)h * NN + r[k]) * CAP2 + p[k]],
                           *(const int2*)&rec[k]);
        }
    }
}

// ---------------------------------------------------------------------------
// Compacted-ELL SpMM + fused message dropout. FULL WARP PER ROW, float2/lane.
// Chunk of 32 records loaded coalesced (lanes past n hold {0,0}); edge j is
// broadcast with 2 shuffles — NO ballot/ffs/select: shuffles past the row end
// yield col=0, v=0 (gather of node 0 times 0 = benign). Unroll 4 keeps four
// independent gathers in flight. Register accumulator, no atomics.
// ---------------------------------------------------------------------------
__global__ void spmm_hop_kernel(const float* __restrict__ src,   // = out + hop*64
                                const float* __restrict__ mrand, // hop slice
                                float* __restrict__ out,
                                int hop) {
    const int lane = threadIdx.x & 31;
    const int gw   = (blockIdx.x * blockDim.x + threadIdx.x) >> 5;
    const int nw   = (gridDim.x * blockDim.x) >> 5;
    const float sc = 1.0f / 0.9f;
    const int*  __restrict__ cnt   = g_cnt3 + hop * NN;
    const int2* __restrict__ elist = g_edges3 + (size_t)hop * NN * CAP2;

    for (int r = gw; r < NN; r += nw) {
        const int n = __ldg(cnt + r);
        const int2* __restrict__ eb = elist + (size_t)r * CAP2;
        float accx = 0.f, accy = 0.f;
        for (int b = 0; b < n; b += 32) {
            int i = b + lane;
            int2 ed = (i < n) ? __ldg(eb + i) : make_int2(0, 0);
            int lim  = n - b; if (lim > 32) lim = 32;
            int lim4 = (lim + 3) & ~3;           // shuffles past lim give {0,0}
            for (int j = 0; j < lim4; j += 4) {
                int   c0 = __shfl_sync(0xFFFFFFFFu, ed.x, j);
                float v0 = __int_as_float(__shfl_sync(0xFFFFFFFFu, ed.y, j));
                int   c1 = __shfl_sync(0xFFFFFFFFu, ed.x, j + 1);
                float v1 = __int_as_float(__shfl_sync(0xFFFFFFFFu, ed.y, j + 1));
                int   c2 = __shfl_sync(0xFFFFFFFFu, ed.x, j + 2);
                float v2 = __int_as_float(__shfl_sync(0xFFFFFFFFu, ed.y, j + 2));
                int   c3 = __shfl_sync(0xFFFFFFFFu, ed.x, j + 3);
                float v3 = __int_as_float(__shfl_sync(0xFFFFFFFFu, ed.y, j + 3));
                float2 x0 = __ldg((const float2*)(src + (size_t)c0 * 256) + lane);
                float2 x1 = __ldg((const float2*)(src + (size_t)c1 * 256) + lane);
                float2 x2 = __ldg((const float2*)(src + (size_t)c2 * 256) + lane);
                float2 x3 = __ldg((const float2*)(src + (size_t)c3 * 256) + lane);
                accx += v0 * x0.x; accy += v0 * x0.y;
                accx += v1 * x1.x; accy += v1 * x1.y;
                accx += v2 * x2.x; accy += v2 * x2.y;
                accx += v3 * x3.x; accy += v3 * x3.y;
            }
        }
        // fused message dropout + write next hop slice (sole owner of row r)
        float2 m = __ldcs((const float2*)(mrand + (size_t)r * 64) + lane);
        float2 o;
        o.x = (m.x >= 0.1f) ? accx * sc : 0.f;
        o.y = (m.y >= 0.1f) ? accy * sc : 0.f;
        ((float2*)(out + (size_t)r * 256 + (size_t)(hop + 1) * 64))[lane] = o;
    }
}

// ---------------------------------------------------------------------------
extern "C" void kernel_launch(void* const* d_in, const int* in_sizes, int n_in,
                              void* d_out, int out_size) {
    const float* user  = (const float*)d_in[0];
    const float* item  = (const float*)d_in[1];
    const int*   rows  = (const int*)  d_in[2];
    const int*   cols  = (const int*)  d_in[3];
    const float* vals  = (const float*)d_in[4];
    const float* erand = (const float*)d_in[5];
    const float* mrand = (const float*)d_in[6];
    float*       out   = (float*)d_out;

    const int totalT    = NN * D / 16;      // 600,000
    const int ewThreads = 256;
    const int ewBlocks  = (totalT + ewThreads - 1) / ewThreads;

    const int gsBlocks  = 148 * 32;
    const int gsThreads = 256;

    // Launches: 0 dummy, 1 init, 2 build, 3 hop0, 4 hop1, 5 hop2
    // (ncu -s 5 -c 1 -> profiles spmm_hop hop 2)
    dummy_kernel<<<1, 32>>>();
    init_kernel<<<ewBlocks, ewThreads>>>(user, item, out);
    build_kernel<<<gsBlocks, gsThreads>>>(rows, cols, vals, erand);
    for (int hop = 0; hop < HOPS; ++hop) {
        spmm_hop_kernel<<<gsBlocks, gsThreads>>>(out + (size_t)hop * 64,
                                                 mrand + (size_t)hop * NN * D,
                                                 out, hop);
    }
}